// round 10
// baseline (speedup 1.0000x reference)
#include <cuda_runtime.h>

#define NN 50000
#define NE 1000000
#define NH 8

// ---------------- static device scratch ----------------
__device__ float g_H[NN * 512];
__device__ float g_s1[NN * NH];
__device__ float g_s2[NN * NH];
__device__ float g_h2[NN * 64];
__device__ float g_t1[NN];
__device__ float g_t2[NN];
__device__ float g_w12[16 * 64];
__device__ int   g_counts[NN];
__device__ int   g_cursor[NN];
__device__ int   g_offsets[NN + 1];
__device__ int   g_bsum[64];
__device__ int   g_src_sorted[NE];
__device__ int   g_tgt_sorted[NE];
__device__ float g_wgt_sorted[NE * NH];   // layer-1 per-edge per-head weights
__device__ float g_ea2_sorted[NE];        // ea.a3 -> (after k_wgt2) layer-2 weights

__device__ __forceinline__ float leaky(float x) { return x >= 0.f ? x : 0.01f * x; }
__device__ __forceinline__ float elu1(float x)  { return x > 0.f ? x : expm1f(x); }

__device__ __forceinline__ unsigned long long packdup(float a) {
    unsigned long long p;
    asm("mov.b64 %0, {%1, %1};" : "=l"(p) : "f"(a));
    return p;
}
__device__ __forceinline__ void ffma2(unsigned long long& c, unsigned long long a,
                                      unsigned long long b) {
    asm("fma.rn.f32x2 %0, %1, %2, %0;" : "+l"(c) : "l"(a), "l"(b));
}

// ---------------- pre: zero counts + w12 ----------------
__global__ void k_pre(const float* __restrict__ Wh, const float* __restrict__ ah) {
    int i = blockIdx.x * 1024 + threadIdx.x;
    if (i < NN) { g_counts[i] = 0; g_cursor[i] = 0; }
    if (blockIdx.x == 0) {
        int t = threadIdx.x;
        int which = t >> 9, h = (t >> 6) & 7, k = t & 63;
        const float* wrow = Wh + h * 4096 + k * 64;
        const float* a = ah + h * 144 + which * 64;
        float s = 0.f;
#pragma unroll 16
        for (int j = 0; j < 64; j++) s = fmaf(wrow[j], a[j], s);
        g_w12[(which * 8 + h) * 64 + k] = s;
    }
}

// ---------------- s1/s2 ----------------
__global__ __launch_bounds__(256) void k_s12(const float* __restrict__ X) {
    __shared__ float Xs[64 * 65];
    __shared__ float Ws[64 * 17];
    int t = threadIdx.x;
    int r0 = blockIdx.x * 64;
#pragma unroll
    for (int i = 0; i < 16; i++) {
        int idx = i * 256 + t;
        int rr = idx >> 6, cc = idx & 63;
        Xs[rr * 65 + cc] = (r0 + rr < NN) ? X[(r0 + rr) * 64 + cc] : 0.f;
    }
#pragma unroll
    for (int i = 0; i < 4; i++) {
        int idx = i * 256 + t;
        int c = idx >> 6, k = idx & 63;
        Ws[k * 17 + c] = g_w12[idx];
    }
    __syncthreads();
    int r = t >> 2, q = t & 3;
    float acc[4] = {};
    for (int k = 0; k < 64; k++) {
        float xv = Xs[r * 65 + k];
#pragma unroll
        for (int m = 0; m < 4; m++)
            acc[m] = fmaf(xv, Ws[k * 17 + q * 4 + m], acc[m]);
    }
    int n = r0 + r;
    if (n < NN) {
#pragma unroll
        for (int m = 0; m < 4; m++) {
            int c = q * 4 + m;
            if (c < 8) g_s1[n * 8 + c] = acc[m];
            else       g_s2[n * 8 + (c - 8)] = acc[m];
        }
    }
}

// ---------------- histogram ----------------
__global__ void k_hist(const int* __restrict__ src) {
    int e = (blockIdx.x * blockDim.x + threadIdx.x) * 2;
    if (e + 1 < NE) {
        int2 s = *(const int2*)(src + e);
        atomicAdd(&g_counts[s.x], 1);
        atomicAdd(&g_counts[s.y], 1);
    } else if (e < NE) {
        atomicAdd(&g_counts[src[e]], 1);
    }
}

// ---------------- 3-phase scan ----------------
__global__ void k_scan1() {
    __shared__ int ws[32];
    int t = threadIdx.x;
    int i = blockIdx.x * 1024 + t;
    int v = (i < NN) ? g_counts[i] : 0;
    int x = v;
    int lane = t & 31;
#pragma unroll
    for (int o = 1; o < 32; o <<= 1) {
        int y = __shfl_up_sync(0xffffffffu, x, o);
        if (lane >= o) x += y;
    }
    if (lane == 31) ws[t >> 5] = x;
    __syncthreads();
    if (t < 32) {
        int s = ws[t];
#pragma unroll
        for (int o = 1; o < 32; o <<= 1) {
            int y = __shfl_up_sync(0xffffffffu, s, o);
            if (t >= o) s += y;
        }
        ws[t] = s;
    }
    __syncthreads();
    int pre = (t >= 32) ? ws[(t >> 5) - 1] : 0;
    int incl = x + pre;
    if (i < NN) g_offsets[i] = incl - v;
    if (t == 1023) g_bsum[blockIdx.x] = incl;
}

__global__ void k_scan2() {
    if (threadIdx.x == 0) {
        int s = 0;
        for (int i = 0; i < 49; i++) { int c = g_bsum[i]; g_bsum[i] = s; s += c; }
        g_offsets[NN] = s;
    }
}

__global__ void k_scan3() {
    int i = blockIdx.x * 1024 + threadIdx.x;
    if (i < NN) g_offsets[i] += g_bsum[blockIdx.x];
}

// ---------------- scatter: CSR order + layer-1 weights + src_sorted ----------------
__global__ void k_scatter(const int* __restrict__ src, const int* __restrict__ tgt,
                          const float* __restrict__ ea,
                          const float* __restrict__ a_heads,
                          const float* __restrict__ a_out) {
    __shared__ float sA[NH * 16];
    __shared__ float sA2[16];
    int t = threadIdx.x;
    if (t < NH * 16) sA[t] = a_heads[(t >> 4) * 144 + 128 + (t & 15)];
    if (t < 16) sA2[t] = a_out[128 + t];
    __syncthreads();
    int e = blockIdx.x * blockDim.x + t;
    if (e >= NE) return;
    int s  = src[e];
    int tg = tgt[e];
    int p = atomicAdd(&g_cursor[s], 1);
    int idx = g_offsets[s] + p;
    g_tgt_sorted[idx] = tg;
    g_src_sorted[idx] = s;
    float eav[16];
    const float4* ep = (const float4*)(ea + e * 16);
#pragma unroll
    for (int q = 0; q < 4; q++) {
        float4 v = __ldcs(ep + q);
        eav[q * 4 + 0] = v.x; eav[q * 4 + 1] = v.y;
        eav[q * 4 + 2] = v.z; eav[q * 4 + 3] = v.w;
    }
    float d2 = 0.f;
#pragma unroll
    for (int k = 0; k < 16; k++) d2 = fmaf(eav[k], sA2[k], d2);
    __stcs(g_ea2_sorted + idx, d2);
    float4 s1a = *(const float4*)(g_s1 + s * 8);
    float4 s1b = *(const float4*)(g_s1 + s * 8 + 4);
    float4 s2a = *(const float4*)(g_s2 + tg * 8);
    float4 s2b = *(const float4*)(g_s2 + tg * 8 + 4);
    float s1v[8] = {s1a.x, s1a.y, s1a.z, s1a.w, s1b.x, s1b.y, s1b.z, s1b.w};
    float s2v[8] = {s2a.x, s2a.y, s2a.z, s2a.w, s2b.x, s2b.y, s2b.z, s2b.w};
    float wv[8];
#pragma unroll
    for (int h = 0; h < NH; h++) {
        float d = 0.f;
#pragma unroll
        for (int k = 0; k < 16; k++) d = fmaf(eav[k], sA[h * 16 + k], d);
        float sc = s1v[h] + s2v[h] + d;
        wv[h] = __expf(leaky(sc));
    }
    float4* dst = (float4*)(g_wgt_sorted + (size_t)idx * 8);
    __stcs(dst,     make_float4(wv[0], wv[1], wv[2], wv[3]));
    __stcs(dst + 1, make_float4(wv[4], wv[5], wv[6], wv[7]));
}

// ---------------- layer-1 aggregation: precomputed weights ----------------
__global__ __launch_bounds__(256) void k_agg1(const float* __restrict__ X) {
    int w = (blockIdx.x * blockDim.x + threadIdx.x) >> 5;
    if (w >= NN) return;
    int lane = threadIdx.x & 31;
    int beg = g_offsets[w], end = g_offsets[w + 1];
    float acc[8][2] = {};
    float denom = 0.f;
#pragma unroll 4
    for (int i = beg; i < end; i++) {
        int tg = g_tgt_sorted[i];
        float wgt = 0.f;
        if (lane < 8) {
            wgt = g_wgt_sorted[(size_t)i * 8 + lane];
            denom += wgt;
        }
        float2 xv = ((const float2*)(X + tg * 64))[lane];
#pragma unroll
        for (int h = 0; h < 8; h++) {
            float wl = __shfl_sync(0xffffffffu, wgt, h);
            acc[h][0] = fmaf(wl, xv.x, acc[h][0]);
            acc[h][1] = fmaf(wl, xv.y, acc[h][1]);
        }
    }
#pragma unroll
    for (int h = 0; h < 8; h++) {
        float d = __shfl_sync(0xffffffffu, denom, h);
        float inv = 1.f / (d + 1e-16f);
        ((float2*)(g_H + w * 512 + h * 64))[lane] =
            make_float2(acc[h][0] * inv, acc[h][1] * inv);
    }
}

// ---------------- fused GEMM: h2 = elu2(aggH@Wh per head) @ Wout, + t1/t2 ----------------
// smem: sA[128x68] (head slice of g_H), sP[128x68] (projected head), sW[64x68]
#define GSM ((128 + 128 + 64) * 68)
__global__ __launch_bounds__(256) void k_gemmF(const float* __restrict__ Wh,
                                               const float* __restrict__ Wo,
                                               const float* __restrict__ a_out) {
    extern __shared__ float sm[];
    float* sA = sm;                    // [128][68]
    float* sP = sm + 128 * 68;         // [128][68]
    float* sW = sm + 256 * 68;         // [64][68]
    int t = threadIdx.x;
    int r0 = blockIdx.x * 128;
    int ty = t >> 3, tx = t & 7;       // 4 rows x 8 cols per thread
    unsigned long long acc2[4][4] = {};

    for (int h = 0; h < 8; h++) {
        __syncthreads();
        // stage sA = g_H head slice, sW = W_h
#pragma unroll
        for (int i = 0; i < 8; i++) {
            int idx = i * 256 + t;
            int m = idx >> 4, kq = idx & 15;
            float4 v = make_float4(0, 0, 0, 0);
            if (r0 + m < NN) v = *(const float4*)(g_H + (r0 + m) * 512 + h * 64 + kq * 4);
            *(float4*)(sA + m * 68 + kq * 4) = v;
        }
#pragma unroll
        for (int i = 0; i < 4; i++) {
            int idx = i * 256 + t;
            int k = idx >> 4, jq = idx & 15;
            *(float4*)(sW + k * 68 + jq * 4) = *(const float4*)(Wh + h * 4096 + k * 64 + jq * 4);
        }
        __syncthreads();
        // P = sA @ W_h  (thread tile 4x8, f32x2)
        unsigned long long pacc[4][4] = {};
#pragma unroll 4
        for (int k = 0; k < 64; k++) {
            float4 b0 = *(float4*)(sW + k * 68 + tx * 8);
            float4 b1 = *(float4*)(sW + k * 68 + tx * 8 + 4);
            unsigned long long bb[4];
            bb[0] = *(unsigned long long*)&b0.x; bb[1] = *(unsigned long long*)&b0.z;
            bb[2] = *(unsigned long long*)&b1.x; bb[3] = *(unsigned long long*)&b1.z;
#pragma unroll
            for (int i = 0; i < 4; i++) {
                unsigned long long pa = packdup(sA[(ty * 4 + i) * 68 + k]);
#pragma unroll
                for (int j = 0; j < 4; j++) ffma2(pacc[i][j], pa, bb[j]);
            }
        }
        // write elu2(P) to sP
#pragma unroll
        for (int i = 0; i < 4; i++) {
            float o[8];
#pragma unroll
            for (int j = 0; j < 4; j++) {
                float2 p = *(float2*)&pacc[i][j];
                o[2 * j] = elu1(elu1(p.x)); o[2 * j + 1] = elu1(elu1(p.y));
            }
            float4* d = (float4*)(sP + (ty * 4 + i) * 68 + tx * 8);
            d[0] = make_float4(o[0], o[1], o[2], o[3]);
            d[1] = make_float4(o[4], o[5], o[6], o[7]);
        }
        __syncthreads();
        // restage sW = Wout rows [h*64, h*64+64)
#pragma unroll
        for (int i = 0; i < 4; i++) {
            int idx = i * 256 + t;
            int k = idx >> 4, jq = idx & 15;
            *(float4*)(sW + k * 68 + jq * 4) = *(const float4*)(Wo + (h * 64 + k) * 64 + jq * 4);
        }
        __syncthreads();
        // h2 += P @ Wout_h
#pragma unroll 4
        for (int k = 0; k < 64; k++) {
            float4 b0 = *(float4*)(sW + k * 68 + tx * 8);
            float4 b1 = *(float4*)(sW + k * 68 + tx * 8 + 4);
            unsigned long long bb[4];
            bb[0] = *(unsigned long long*)&b0.x; bb[1] = *(unsigned long long*)&b0.z;
            bb[2] = *(unsigned long long*)&b1.x; bb[3] = *(unsigned long long*)&b1.z;
#pragma unroll
            for (int i = 0; i < 4; i++) {
                unsigned long long pa = packdup(sP[(ty * 4 + i) * 68 + k]);
#pragma unroll
                for (int j = 0; j < 4; j++) ffma2(acc2[i][j], pa, bb[j]);
            }
        }
    }
    // epilogue: h2 + t1/t2
#pragma unroll
    for (int i = 0; i < 4; i++) {
        int row = r0 + ty * 4 + i;
        float o[8];
#pragma unroll
        for (int j = 0; j < 4; j++) {
            float2 p = *(float2*)&acc2[i][j];
            o[2 * j] = p.x; o[2 * j + 1] = p.y;
        }
        float p1 = 0.f, p2 = 0.f;
#pragma unroll
        for (int j = 0; j < 8; j++) {
            p1 = fmaf(o[j], __ldg(a_out + tx * 8 + j), p1);
            p2 = fmaf(o[j], __ldg(a_out + 64 + tx * 8 + j), p2);
        }
#pragma unroll
        for (int off = 4; off > 0; off >>= 1) {
            p1 += __shfl_down_sync(0xffffffffu, p1, off, 8);
            p2 += __shfl_down_sync(0xffffffffu, p2, off, 8);
        }
        if (row < NN) {
            float4* dst = (float4*)(g_h2 + row * 64 + tx * 8);
            dst[0] = make_float4(o[0], o[1], o[2], o[3]);
            dst[1] = make_float4(o[4], o[5], o[6], o[7]);
            if (tx == 0) { g_t1[row] = p1; g_t2[row] = p2; }
        }
    }
}

// ---------------- layer-2 edge weights (in-place over ea2_sorted) ----------------
__global__ void k_wgt2() {
    int i = blockIdx.x * blockDim.x + threadIdx.x;
    if (i >= NE) return;
    int s  = g_src_sorted[i];
    int tg = g_tgt_sorted[i];
    float sc = leaky(g_t1[s] + g_t2[tg] + g_ea2_sorted[i]);
    g_ea2_sorted[i] = __expf(sc);
}

// ---------------- layer-2 aggregation + log_softmax: tight loop ----------------
__global__ __launch_bounds__(256) void k_agg2(float* __restrict__ out) {
    int n = (blockIdx.x * blockDim.x + threadIdx.x) >> 5;
    if (n >= NN) return;
    int lane = threadIdx.x & 31;
    int beg = g_offsets[n], end = g_offsets[n + 1];
    float acc0 = 0.f, acc1 = 0.f, denom = 0.f;
#pragma unroll 4
    for (int i = beg; i < end; i++) {
        int tg = g_tgt_sorted[i];
        float wgt = g_ea2_sorted[i];
        denom += wgt;
        float2 hv = ((const float2*)(g_h2 + tg * 64))[lane];
        acc0 = fmaf(wgt, hv.x, acc0);
        acc1 = fmaf(wgt, hv.y, acc1);
    }
    float inv = 1.f / (denom + 1e-16f);
    float y0 = elu1(acc0 * inv);
    float y1 = elu1(acc1 * inv);
    float m = fmaxf(y0, y1);
#pragma unroll
    for (int o = 16; o > 0; o >>= 1) m = fmaxf(m, __shfl_xor_sync(0xffffffffu, m, o));
    float se = __expf(y0 - m) + __expf(y1 - m);
#pragma unroll
    for (int o = 16; o > 0; o >>= 1) se += __shfl_xor_sync(0xffffffffu, se, o);
    float ls = m + logf(se);
    ((float2*)(out + n * 64))[lane] = make_float2(y0 - ls, y1 - ls);
}

// ---------------- launcher ----------------
extern "C" void kernel_launch(void* const* d_in, const int* in_sizes, int n_in,
                              void* d_out, int out_size) {
    const float* X        = (const float*)d_in[0];
    const float* ea       = (const float*)d_in[1];
    const float* W_heads  = (const float*)d_in[2];
    const float* a_heads  = (const float*)d_in[3];
    const float* W_out    = (const float*)d_in[4];
    const float* a_out    = (const float*)d_in[5];
    const int*   eidx     = (const int*)d_in[6];
    const int* src = eidx;
    const int* tgt = eidx + NE;
    float* out = (float*)d_out;

    size_t gsm = GSM * sizeof(float);
    cudaFuncSetAttribute(k_gemmF, cudaFuncAttributeMaxDynamicSharedMemorySize, gsm);

    k_pre<<<49, 1024>>>(W_heads, a_heads);          // 0
    k_s12<<<(NN + 63) / 64, 256>>>(X);              // 1
    k_hist<<<(NE / 2 + 255) / 256, 256>>>(src);     // 2
    k_scan1<<<49, 1024>>>();                        // 3
    k_scan2<<<1, 32>>>();                           // 4
    k_scan3<<<49, 1024>>>();                        // 5
    k_scatter<<<(NE + 255) / 256, 256>>>(src, tgt, ea, a_heads, a_out);  // 6
    k_agg1<<<(NN * 32 + 255) / 256, 256>>>(X);      // 7
    k_gemmF<<<(NN + 127) / 128, 256, gsm>>>(W_heads, W_out, a_out);      // 8
    k_wgt2<<<(NE + 255) / 256, 256>>>();            // 9
    k_agg2<<<(NN * 32 + 255) / 256, 256>>>(out);    // 10
}

// round 11
// speedup vs baseline: 1.1088x; 1.1088x over previous
#include <cuda_runtime.h>
#include <cstdint>

#define NN 50000
#define NE 1000000
#define NH 8

// ---------------- static device scratch ----------------
__device__ float g_H[NN * 512];
__device__ float g_s1[NN * NH];
__device__ float g_s2[NN * NH];
__device__ float g_h2[NN * 64];
__device__ float g_t1[NN];
__device__ float g_t2[NN];
__device__ float g_w12[16 * 64];
__device__ int   g_counts[NN];
__device__ int   g_cursor[NN];
__device__ int   g_offsets[NN + 1];
__device__ int   g_bsum[64];
__device__ int   g_src_sorted[NE];
__device__ int   g_tgt_sorted[NE];
__device__ float g_wgt_sorted[NE * NH];
__device__ float g_ea2_sorted[NE];

__device__ __forceinline__ float leaky(float x) { return x >= 0.f ? x : 0.01f * x; }
__device__ __forceinline__ float elu1(float x)  { return x > 0.f ? x : expm1f(x); }

// tf32 helpers
__device__ __forceinline__ uint32_t tf32_rna(float x) {
    uint32_t r;
    asm("cvt.rna.tf32.f32 %0, %1;" : "=r"(r) : "f"(x));
    return r;
}
__device__ __forceinline__ void tf32_split(float x, uint32_t& hi, uint32_t& lo) {
    hi = tf32_rna(x);
    float rem = x - __uint_as_float(hi);
    lo = tf32_rna(rem);
}
__device__ __forceinline__ void mma_tf32(float* c, const uint32_t* a, uint32_t b0, uint32_t b1) {
    asm volatile(
        "mma.sync.aligned.m16n8k8.row.col.f32.tf32.tf32.f32 "
        "{%0,%1,%2,%3}, {%4,%5,%6,%7}, {%8,%9}, {%0,%1,%2,%3};"
        : "+f"(c[0]), "+f"(c[1]), "+f"(c[2]), "+f"(c[3])
        : "r"(a[0]), "r"(a[1]), "r"(a[2]), "r"(a[3]), "r"(b0), "r"(b1));
}

// ---------------- pre: zero counts + w12 ----------------
__global__ void k_pre(const float* __restrict__ Wh, const float* __restrict__ ah) {
    int i = blockIdx.x * 1024 + threadIdx.x;
    if (i < NN) { g_counts[i] = 0; g_cursor[i] = 0; }
    if (blockIdx.x == 0) {
        int t = threadIdx.x;
        int which = t >> 9, h = (t >> 6) & 7, k = t & 63;
        const float* wrow = Wh + h * 4096 + k * 64;
        const float* a = ah + h * 144 + which * 64;
        float s = 0.f;
#pragma unroll 16
        for (int j = 0; j < 64; j++) s = fmaf(wrow[j], a[j], s);
        g_w12[(which * 8 + h) * 64 + k] = s;
    }
}

// ---------------- s1/s2 ----------------
__global__ __launch_bounds__(256) void k_s12(const float* __restrict__ X) {
    __shared__ float Xs[64 * 65];
    __shared__ float Ws[64 * 17];
    int t = threadIdx.x;
    int r0 = blockIdx.x * 64;
#pragma unroll
    for (int i = 0; i < 16; i++) {
        int idx = i * 256 + t;
        int rr = idx >> 6, cc = idx & 63;
        Xs[rr * 65 + cc] = (r0 + rr < NN) ? X[(r0 + rr) * 64 + cc] : 0.f;
    }
#pragma unroll
    for (int i = 0; i < 4; i++) {
        int idx = i * 256 + t;
        int c = idx >> 6, k = idx & 63;
        Ws[k * 17 + c] = g_w12[idx];
    }
    __syncthreads();
    int r = t >> 2, q = t & 3;
    float acc[4] = {};
    for (int k = 0; k < 64; k++) {
        float xv = Xs[r * 65 + k];
#pragma unroll
        for (int m = 0; m < 4; m++)
            acc[m] = fmaf(xv, Ws[k * 17 + q * 4 + m], acc[m]);
    }
    int n = r0 + r;
    if (n < NN) {
#pragma unroll
        for (int m = 0; m < 4; m++) {
            int c = q * 4 + m;
            if (c < 8) g_s1[n * 8 + c] = acc[m];
            else       g_s2[n * 8 + (c - 8)] = acc[m];
        }
    }
}

// ---------------- histogram ----------------
__global__ void k_hist(const int* __restrict__ src) {
    int e = (blockIdx.x * blockDim.x + threadIdx.x) * 2;
    if (e + 1 < NE) {
        int2 s = *(const int2*)(src + e);
        atomicAdd(&g_counts[s.x], 1);
        atomicAdd(&g_counts[s.y], 1);
    } else if (e < NE) {
        atomicAdd(&g_counts[src[e]], 1);
    }
}

// ---------------- 3-phase scan ----------------
__global__ void k_scan1() {
    __shared__ int ws[32];
    int t = threadIdx.x;
    int i = blockIdx.x * 1024 + t;
    int v = (i < NN) ? g_counts[i] : 0;
    int x = v;
    int lane = t & 31;
#pragma unroll
    for (int o = 1; o < 32; o <<= 1) {
        int y = __shfl_up_sync(0xffffffffu, x, o);
        if (lane >= o) x += y;
    }
    if (lane == 31) ws[t >> 5] = x;
    __syncthreads();
    if (t < 32) {
        int s = ws[t];
#pragma unroll
        for (int o = 1; o < 32; o <<= 1) {
            int y = __shfl_up_sync(0xffffffffu, s, o);
            if (t >= o) s += y;
        }
        ws[t] = s;
    }
    __syncthreads();
    int pre = (t >= 32) ? ws[(t >> 5) - 1] : 0;
    int incl = x + pre;
    if (i < NN) g_offsets[i] = incl - v;
    if (t == 1023) g_bsum[blockIdx.x] = incl;
}

__global__ void k_scan2() {
    if (threadIdx.x == 0) {
        int s = 0;
        for (int i = 0; i < 49; i++) { int c = g_bsum[i]; g_bsum[i] = s; s += c; }
        g_offsets[NN] = s;
    }
}

__global__ void k_scan3() {
    int i = blockIdx.x * 1024 + threadIdx.x;
    if (i < NN) g_offsets[i] += g_bsum[blockIdx.x];
}

// ---------------- scatter: CSR order + layer-1 weights + src_sorted ----------------
__global__ void k_scatter(const int* __restrict__ src, const int* __restrict__ tgt,
                          const float* __restrict__ ea,
                          const float* __restrict__ a_heads,
                          const float* __restrict__ a_out) {
    __shared__ float sA[NH * 16];
    __shared__ float sA2[16];
    int t = threadIdx.x;
    if (t < NH * 16) sA[t] = a_heads[(t >> 4) * 144 + 128 + (t & 15)];
    if (t < 16) sA2[t] = a_out[128 + t];
    __syncthreads();
    int e = blockIdx.x * blockDim.x + t;
    if (e >= NE) return;
    int s  = src[e];
    int tg = tgt[e];
    int p = atomicAdd(&g_cursor[s], 1);
    int idx = g_offsets[s] + p;
    g_tgt_sorted[idx] = tg;
    g_src_sorted[idx] = s;
    float eav[16];
    const float4* ep = (const float4*)(ea + e * 16);
#pragma unroll
    for (int q = 0; q < 4; q++) {
        float4 v = __ldcs(ep + q);
        eav[q * 4 + 0] = v.x; eav[q * 4 + 1] = v.y;
        eav[q * 4 + 2] = v.z; eav[q * 4 + 3] = v.w;
    }
    float d2 = 0.f;
#pragma unroll
    for (int k = 0; k < 16; k++) d2 = fmaf(eav[k], sA2[k], d2);
    __stcs(g_ea2_sorted + idx, d2);
    float4 s1a = *(const float4*)(g_s1 + s * 8);
    float4 s1b = *(const float4*)(g_s1 + s * 8 + 4);
    float4 s2a = *(const float4*)(g_s2 + tg * 8);
    float4 s2b = *(const float4*)(g_s2 + tg * 8 + 4);
    float s1v[8] = {s1a.x, s1a.y, s1a.z, s1a.w, s1b.x, s1b.y, s1b.z, s1b.w};
    float s2v[8] = {s2a.x, s2a.y, s2a.z, s2a.w, s2b.x, s2b.y, s2b.z, s2b.w};
    float wv[8];
#pragma unroll
    for (int h = 0; h < NH; h++) {
        float d = 0.f;
#pragma unroll
        for (int k = 0; k < 16; k++) d = fmaf(eav[k], sA[h * 16 + k], d);
        float sc = s1v[h] + s2v[h] + d;
        wv[h] = __expf(leaky(sc));
    }
    float4* dst = (float4*)(g_wgt_sorted + (size_t)idx * 8);
    __stcs(dst,     make_float4(wv[0], wv[1], wv[2], wv[3]));
    __stcs(dst + 1, make_float4(wv[4], wv[5], wv[6], wv[7]));
}

// ---------------- layer-1 aggregation: precomputed weights ----------------
__global__ __launch_bounds__(256) void k_agg1(const float* __restrict__ X) {
    int w = (blockIdx.x * blockDim.x + threadIdx.x) >> 5;
    if (w >= NN) return;
    int lane = threadIdx.x & 31;
    int beg = g_offsets[w], end = g_offsets[w + 1];
    float acc[8][2] = {};
    float denom = 0.f;
#pragma unroll 4
    for (int i = beg; i < end; i++) {
        int tg = g_tgt_sorted[i];
        float wgt = 0.f;
        if (lane < 8) {
            wgt = g_wgt_sorted[(size_t)i * 8 + lane];
            denom += wgt;
        }
        float2 xv = ((const float2*)(X + tg * 64))[lane];
#pragma unroll
        for (int h = 0; h < 8; h++) {
            float wl = __shfl_sync(0xffffffffu, wgt, h);
            acc[h][0] = fmaf(wl, xv.x, acc[h][0]);
            acc[h][1] = fmaf(wl, xv.y, acc[h][1]);
        }
    }
#pragma unroll
    for (int h = 0; h < 8; h++) {
        float d = __shfl_sync(0xffffffffu, denom, h);
        float inv = 1.f / (d + 1e-16f);
        ((float2*)(g_H + w * 512 + h * 64))[lane] =
            make_float2(acc[h][0] * inv, acc[h][1] * inv);
    }
}

// ---------------- fused GEMM via tf32x3 tensor cores ----------------
// smem: sA [128][68] staged g_H head slice; sW1 [64][68] = W_h; sW2 [64][68] = Wout chunk;
//       sP 8 warps x [16][68] warp-private projected tile.
#define SM_A  0
#define SM_W1 (128 * 68)
#define SM_W2 (SM_W1 + 64 * 68)
#define SM_P  (SM_W2 + 64 * 68)
#define GSMF  (SM_P + 8 * 16 * 68)
__global__ __launch_bounds__(256) void k_gemmF(const float* __restrict__ Wh,
                                               const float* __restrict__ Wo,
                                               const float* __restrict__ a_out) {
    extern __shared__ float sm[];
    float* sA  = sm + SM_A;
    float* sW1 = sm + SM_W1;
    float* sW2 = sm + SM_W2;
    int t = threadIdx.x;
    int r0 = blockIdx.x * 128;
    int warp = t >> 5, lane = t & 31;
    int g = lane >> 2, q = lane & 3;        // group / thread-in-group
    int wm = warp * 16;                     // warp's row base in tile
    float* sPw = sm + SM_P + warp * (16 * 68);

    float C2[8][4] = {};                    // persistent: h2 tile rows {wm+g, wm+g+8}

    for (int h = 0; h < 8; h++) {
        __syncthreads();
        // stage sA = g_H[:, h*64:(h+1)*64]
#pragma unroll
        for (int i = 0; i < 8; i++) {
            int idx = i * 256 + t;
            int m = idx >> 4, kq = idx & 15;
            float4 v = make_float4(0, 0, 0, 0);
            if (r0 + m < NN) v = *(const float4*)(g_H + (r0 + m) * 512 + h * 64 + kq * 4);
            *(float4*)(sA + m * 68 + kq * 4) = v;
        }
        // stage sW1 = W_h (64x64 row-major [k][n]), sW2 = Wout rows [h*64 .. h*64+64)
#pragma unroll
        for (int i = 0; i < 4; i++) {
            int idx = i * 256 + t;
            int k = idx >> 4, jq = idx & 15;
            *(float4*)(sW1 + k * 68 + jq * 4) = *(const float4*)(Wh + h * 4096 + k * 64 + jq * 4);
            *(float4*)(sW2 + k * 68 + jq * 4) = *(const float4*)(Wo + (h * 64 + k) * 64 + jq * 4);
        }
        __syncthreads();

        // ---- GEMM1: C1 = sA(warp rows) @ sW1, tf32x3 ----
        float C1[8][4] = {};
        for (int ks = 0; ks < 8; ks++) {
            int k0 = ks * 8;
            uint32_t ah[4], al[4];
            {
                const float* Ar = sA + (wm + g) * 68 + k0 + q;
                float a0 = Ar[0], a1 = Ar[8 * 68], a2 = Ar[4], a3 = Ar[8 * 68 + 4];
                tf32_split(a0, ah[0], al[0]);
                tf32_split(a1, ah[1], al[1]);
                tf32_split(a2, ah[2], al[2]);
                tf32_split(a3, ah[3], al[3]);
            }
#pragma unroll
            for (int nt = 0; nt < 8; nt++) {
                float b0f = sW1[(k0 + q) * 68 + nt * 8 + g];
                float b1f = sW1[(k0 + q + 4) * 68 + nt * 8 + g];
                uint32_t bh0, bl0, bh1, bl1;
                tf32_split(b0f, bh0, bl0);
                tf32_split(b1f, bh1, bl1);
                mma_tf32(C1[nt], ah, bh0, bh1);
                mma_tf32(C1[nt], ah, bl0, bl1);
                mma_tf32(C1[nt], al, bh0, bh1);
            }
        }
        // ---- elu^2 -> warp-private sP ----
#pragma unroll
        for (int nt = 0; nt < 8; nt++) {
            *(float2*)(sPw + g * 68 + nt * 8 + 2 * q) =
                make_float2(elu1(elu1(C1[nt][0])), elu1(elu1(C1[nt][1])));
            *(float2*)(sPw + (g + 8) * 68 + nt * 8 + 2 * q) =
                make_float2(elu1(elu1(C1[nt][2])), elu1(elu1(C1[nt][3])));
        }
        __syncwarp();

        // ---- GEMM2: C2 += sPw @ sW2, tf32x3 ----
        for (int ks = 0; ks < 8; ks++) {
            int k0 = ks * 8;
            uint32_t ah[4], al[4];
            {
                const float* Pr = sPw + g * 68 + k0 + q;
                float a0 = Pr[0], a1 = Pr[8 * 68], a2 = Pr[4], a3 = Pr[8 * 68 + 4];
                tf32_split(a0, ah[0], al[0]);
                tf32_split(a1, ah[1], al[1]);
                tf32_split(a2, ah[2], al[2]);
                tf32_split(a3, ah[3], al[3]);
            }
#pragma unroll
            for (int nt = 0; nt < 8; nt++) {
                float b0f = sW2[(k0 + q) * 68 + nt * 8 + g];
                float b1f = sW2[(k0 + q + 4) * 68 + nt * 8 + g];
                uint32_t bh0, bl0, bh1, bl1;
                tf32_split(b0f, bh0, bl0);
                tf32_split(b1f, bh1, bl1);
                mma_tf32(C2[nt], ah, bh0, bh1);
                mma_tf32(C2[nt], ah, bl0, bl1);
                mma_tf32(C2[nt], al, bh0, bh1);
            }
        }
        __syncwarp();
    }

    // ---- epilogue: h2 rows {r0+wm+g, r0+wm+g+8}; fused t1/t2 ----
    int rowA = r0 + wm + g;
    int rowB = rowA + 8;
    float p1a = 0.f, p2a = 0.f, p1b = 0.f, p2b = 0.f;
#pragma unroll
    for (int nt = 0; nt < 8; nt++) {
        int c = nt * 8 + 2 * q;
        float w0 = __ldg(a_out + c), w1 = __ldg(a_out + c + 1);
        float v0 = __ldg(a_out + 64 + c), v1 = __ldg(a_out + 64 + c + 1);
        p1a += C2[nt][0] * w0 + C2[nt][1] * w1;
        p2a += C2[nt][0] * v0 + C2[nt][1] * v1;
        p1b += C2[nt][2] * w0 + C2[nt][3] * w1;
        p2b += C2[nt][2] * v0 + C2[nt][3] * v1;
        if (rowA < NN)
            *(float2*)(g_h2 + rowA * 64 + c) = make_float2(C2[nt][0], C2[nt][1]);
        if (rowB < NN)
            *(float2*)(g_h2 + rowB * 64 + c) = make_float2(C2[nt][2], C2[nt][3]);
    }
    // reduce across the 4 lanes of each group (width 4)
#pragma unroll
    for (int off = 2; off > 0; off >>= 1) {
        p1a += __shfl_down_sync(0xffffffffu, p1a, off, 4);
        p2a += __shfl_down_sync(0xffffffffu, p2a, off, 4);
        p1b += __shfl_down_sync(0xffffffffu, p1b, off, 4);
        p2b += __shfl_down_sync(0xffffffffu, p2b, off, 4);
    }
    if (q == 0) {
        if (rowA < NN) { g_t1[rowA] = p1a; g_t2[rowA] = p2a; }
        if (rowB < NN) { g_t1[rowB] = p1b; g_t2[rowB] = p2b; }
    }
}

// ---------------- layer-2 edge weights (in-place) ----------------
__global__ void k_wgt2() {
    int i = blockIdx.x * blockDim.x + threadIdx.x;
    if (i >= NE) return;
    int s  = g_src_sorted[i];
    int tg = g_tgt_sorted[i];
    float sc = leaky(g_t1[s] + g_t2[tg] + g_ea2_sorted[i]);
    g_ea2_sorted[i] = __expf(sc);
}

// ---------------- layer-2 aggregation + log_softmax ----------------
__global__ __launch_bounds__(256) void k_agg2(float* __restrict__ out) {
    int n = (blockIdx.x * blockDim.x + threadIdx.x) >> 5;
    if (n >= NN) return;
    int lane = threadIdx.x & 31;
    int beg = g_offsets[n], end = g_offsets[n + 1];
    float acc0 = 0.f, acc1 = 0.f, denom = 0.f;
#pragma unroll 4
    for (int i = beg; i < end; i++) {
        int tg = g_tgt_sorted[i];
        float wgt = g_ea2_sorted[i];
        denom += wgt;
        float2 hv = ((const float2*)(g_h2 + tg * 64))[lane];
        acc0 = fmaf(wgt, hv.x, acc0);
        acc1 = fmaf(wgt, hv.y, acc1);
    }
    float inv = 1.f / (denom + 1e-16f);
    float y0 = elu1(acc0 * inv);
    float y1 = elu1(acc1 * inv);
    float m = fmaxf(y0, y1);
#pragma unroll
    for (int o = 16; o > 0; o >>= 1) m = fmaxf(m, __shfl_xor_sync(0xffffffffu, m, o));
    float se = __expf(y0 - m) + __expf(y1 - m);
#pragma unroll
    for (int o = 16; o > 0; o >>= 1) se += __shfl_xor_sync(0xffffffffu, se, o);
    float ls = m + logf(se);
    ((float2*)(out + n * 64))[lane] = make_float2(y0 - ls, y1 - ls);
}

// ---------------- launcher ----------------
extern "C" void kernel_launch(void* const* d_in, const int* in_sizes, int n_in,
                              void* d_out, int out_size) {
    const float* X        = (const float*)d_in[0];
    const float* ea       = (const float*)d_in[1];
    const float* W_heads  = (const float*)d_in[2];
    const float* a_heads  = (const float*)d_in[3];
    const float* W_out    = (const float*)d_in[4];
    const float* a_out    = (const float*)d_in[5];
    const int*   eidx     = (const int*)d_in[6];
    const int* src = eidx;
    const int* tgt = eidx + NE;
    float* out = (float*)d_out;

    size_t gsm = GSMF * sizeof(float);
    cudaFuncSetAttribute(k_gemmF, cudaFuncAttributeMaxDynamicSharedMemorySize, gsm);

    k_pre<<<49, 1024>>>(W_heads, a_heads);          // 0
    k_s12<<<(NN + 63) / 64, 256>>>(X);              // 1
    k_hist<<<(NE / 2 + 255) / 256, 256>>>(src);     // 2
    k_scan1<<<49, 1024>>>();                        // 3
    k_scan2<<<1, 32>>>();                           // 4
    k_scan3<<<49, 1024>>>();                        // 5
    k_scatter<<<(NE + 255) / 256, 256>>>(src, tgt, ea, a_heads, a_out);  // 6
    k_agg1<<<(NN * 32 + 255) / 256, 256>>>(X);      // 7
    k_gemmF<<<(NN + 127) / 128, 256, gsm>>>(W_heads, W_out, a_out);      // 8
    k_wgt2<<<(NE + 255) / 256, 256>>>();            // 9
    k_agg2<<<(NN * 32 + 255) / 256, 256>>>(out);    // 10
}

// round 12
// speedup vs baseline: 1.1093x; 1.0004x over previous
#include <cuda_runtime.h>
#include <cstdint>

#define NN 50000
#define NE 1000000
#define NH 8

// ---------------- static device scratch ----------------
__device__ float g_H[NN * 512];
__device__ float g_s1[NN * NH];
__device__ float g_s2[NN * NH];
__device__ float g_h2[NN * 64];
__device__ float g_t1[NN];
__device__ float g_t2[NN];
__device__ float g_w12[16 * 64];
__device__ int   g_counts[NN];
__device__ int   g_cursor[NN];
__device__ int   g_offsets[NN + 1];
__device__ int   g_bsum[64];
__device__ int   g_tgt_sorted[NE];
__device__ float g_wgt_sorted[NE * NH];
__device__ float g_ea2_sorted[NE];

__device__ __forceinline__ float leaky(float x) { return x >= 0.f ? x : 0.01f * x; }
__device__ __forceinline__ float elu1(float x)  { return x > 0.f ? x : expm1f(x); }

// tf32 helpers
__device__ __forceinline__ uint32_t tf32_rna(float x) {
    uint32_t r;
    asm("cvt.rna.tf32.f32 %0, %1;" : "=r"(r) : "f"(x));
    return r;
}
__device__ __forceinline__ void tf32_split(float x, uint32_t& hi, uint32_t& lo) {
    hi = tf32_rna(x);
    float rem = x - __uint_as_float(hi);
    lo = tf32_rna(rem);
}
__device__ __forceinline__ void mma_tf32(float* c, const uint32_t* a, uint32_t b0, uint32_t b1) {
    asm volatile(
        "mma.sync.aligned.m16n8k8.row.col.f32.tf32.tf32.f32 "
        "{%0,%1,%2,%3}, {%4,%5,%6,%7}, {%8,%9}, {%0,%1,%2,%3};"
        : "+f"(c[0]), "+f"(c[1]), "+f"(c[2]), "+f"(c[3])
        : "r"(a[0]), "r"(a[1]), "r"(a[2]), "r"(a[3]), "r"(b0), "r"(b1));
}

// ---------------- pre: zero counts + w12 ----------------
__global__ void k_pre(const float* __restrict__ Wh, const float* __restrict__ ah) {
    int i = blockIdx.x * 1024 + threadIdx.x;
    if (i < NN) { g_counts[i] = 0; g_cursor[i] = 0; }
    if (blockIdx.x == 0) {
        int t = threadIdx.x;
        int which = t >> 9, h = (t >> 6) & 7, k = t & 63;
        const float* wrow = Wh + h * 4096 + k * 64;
        const float* a = ah + h * 144 + which * 64;
        float s = 0.f;
#pragma unroll 16
        for (int j = 0; j < 64; j++) s = fmaf(wrow[j], a[j], s);
        g_w12[(which * 8 + h) * 64 + k] = s;
    }
}

// ---------------- s1/s2 ----------------
__global__ __launch_bounds__(256) void k_s12(const float* __restrict__ X) {
    __shared__ float Xs[64 * 65];
    __shared__ float Ws[64 * 17];
    int t = threadIdx.x;
    int r0 = blockIdx.x * 64;
#pragma unroll
    for (int i = 0; i < 16; i++) {
        int idx = i * 256 + t;
        int rr = idx >> 6, cc = idx & 63;
        Xs[rr * 65 + cc] = (r0 + rr < NN) ? X[(r0 + rr) * 64 + cc] : 0.f;
    }
#pragma unroll
    for (int i = 0; i < 4; i++) {
        int idx = i * 256 + t;
        int c = idx >> 6, k = idx & 63;
        Ws[k * 17 + c] = g_w12[idx];
    }
    __syncthreads();
    int r = t >> 2, q = t & 3;
    float acc[4] = {};
    for (int k = 0; k < 64; k++) {
        float xv = Xs[r * 65 + k];
#pragma unroll
        for (int m = 0; m < 4; m++)
            acc[m] = fmaf(xv, Ws[k * 17 + q * 4 + m], acc[m]);
    }
    int n = r0 + r;
    if (n < NN) {
#pragma unroll
        for (int m = 0; m < 4; m++) {
            int c = q * 4 + m;
            if (c < 8) g_s1[n * 8 + c] = acc[m];
            else       g_s2[n * 8 + (c - 8)] = acc[m];
        }
    }
}

// ---------------- histogram ----------------
__global__ void k_hist(const int* __restrict__ src) {
    int e = (blockIdx.x * blockDim.x + threadIdx.x) * 2;
    if (e + 1 < NE) {
        int2 s = *(const int2*)(src + e);
        atomicAdd(&g_counts[s.x], 1);
        atomicAdd(&g_counts[s.y], 1);
    } else if (e < NE) {
        atomicAdd(&g_counts[src[e]], 1);
    }
}

// ---------------- 3-phase scan ----------------
__global__ void k_scan1() {
    __shared__ int ws[32];
    int t = threadIdx.x;
    int i = blockIdx.x * 1024 + t;
    int v = (i < NN) ? g_counts[i] : 0;
    int x = v;
    int lane = t & 31;
#pragma unroll
    for (int o = 1; o < 32; o <<= 1) {
        int y = __shfl_up_sync(0xffffffffu, x, o);
        if (lane >= o) x += y;
    }
    if (lane == 31) ws[t >> 5] = x;
    __syncthreads();
    if (t < 32) {
        int s = ws[t];
#pragma unroll
        for (int o = 1; o < 32; o <<= 1) {
            int y = __shfl_up_sync(0xffffffffu, s, o);
            if (t >= o) s += y;
        }
        ws[t] = s;
    }
    __syncthreads();
    int pre = (t >= 32) ? ws[(t >> 5) - 1] : 0;
    int incl = x + pre;
    if (i < NN) g_offsets[i] = incl - v;
    if (t == 1023) g_bsum[blockIdx.x] = incl;
}

__global__ void k_scan2() {
    if (threadIdx.x == 0) {
        int s = 0;
        for (int i = 0; i < 49; i++) { int c = g_bsum[i]; g_bsum[i] = s; s += c; }
        g_offsets[NN] = s;
    }
}

__global__ void k_scan3() {
    int i = blockIdx.x * 1024 + threadIdx.x;
    if (i < NN) g_offsets[i] += g_bsum[blockIdx.x];
}

// ---------------- scatter: CSR order + layer-1 weights ----------------
__global__ void k_scatter(const int* __restrict__ src, const int* __restrict__ tgt,
                          const float* __restrict__ ea,
                          const float* __restrict__ a_heads,
                          const float* __restrict__ a_out) {
    __shared__ float sA[NH * 16];
    __shared__ float sA2[16];
    int t = threadIdx.x;
    if (t < NH * 16) sA[t] = a_heads[(t >> 4) * 144 + 128 + (t & 15)];
    if (t < 16) sA2[t] = a_out[128 + t];
    __syncthreads();
    int e = blockIdx.x * blockDim.x + t;
    if (e >= NE) return;
    int s  = src[e];
    int tg = tgt[e];
    int p = atomicAdd(&g_cursor[s], 1);
    int idx = g_offsets[s] + p;
    g_tgt_sorted[idx] = tg;
    float eav[16];
    const float4* ep = (const float4*)(ea + e * 16);
#pragma unroll
    for (int q = 0; q < 4; q++) {
        float4 v = __ldcs(ep + q);
        eav[q * 4 + 0] = v.x; eav[q * 4 + 1] = v.y;
        eav[q * 4 + 2] = v.z; eav[q * 4 + 3] = v.w;
    }
    float d2 = 0.f;
#pragma unroll
    for (int k = 0; k < 16; k++) d2 = fmaf(eav[k], sA2[k], d2);
    g_ea2_sorted[idx] = d2;
    float4 s1a = *(const float4*)(g_s1 + s * 8);
    float4 s1b = *(const float4*)(g_s1 + s * 8 + 4);
    float4 s2a = *(const float4*)(g_s2 + tg * 8);
    float4 s2b = *(const float4*)(g_s2 + tg * 8 + 4);
    float s1v[8] = {s1a.x, s1a.y, s1a.z, s1a.w, s1b.x, s1b.y, s1b.z, s1b.w};
    float s2v[8] = {s2a.x, s2a.y, s2a.z, s2a.w, s2b.x, s2b.y, s2b.z, s2b.w};
    float wv[8];
#pragma unroll
    for (int h = 0; h < NH; h++) {
        float d = 0.f;
#pragma unroll
        for (int k = 0; k < 16; k++) d = fmaf(eav[k], sA[h * 16 + k], d);
        float sc = s1v[h] + s2v[h] + d;
        wv[h] = __expf(leaky(sc));
    }
    float4* dst = (float4*)(g_wgt_sorted + (size_t)idx * 8);
    dst[0] = make_float4(wv[0], wv[1], wv[2], wv[3]);
    dst[1] = make_float4(wv[4], wv[5], wv[6], wv[7]);
}

// ---------------- layer-1 aggregation: broadcast weight loads, no shfl in loop ----------------
__global__ __launch_bounds__(256) void k_agg1(const float* __restrict__ X) {
    int w = (blockIdx.x * blockDim.x + threadIdx.x) >> 5;
    if (w >= NN) return;
    int lane = threadIdx.x & 31;
    int beg = g_offsets[w], end = g_offsets[w + 1];
    float acc[8][2] = {};
    float denom = 0.f;
#pragma unroll 4
    for (int i = beg; i < end; i++) {
        int tg = g_tgt_sorted[i];
        const float4* wp = (const float4*)(g_wgt_sorted + (size_t)i * 8);
        float4 wa = wp[0];
        float4 wb = wp[1];
        // predicated scalar load for the per-head denominator (same cache line)
        if (lane < 8) denom += g_wgt_sorted[(size_t)i * 8 + lane];
        float2 xv = ((const float2*)(X + tg * 64))[lane];
        acc[0][0] = fmaf(wa.x, xv.x, acc[0][0]); acc[0][1] = fmaf(wa.x, xv.y, acc[0][1]);
        acc[1][0] = fmaf(wa.y, xv.x, acc[1][0]); acc[1][1] = fmaf(wa.y, xv.y, acc[1][1]);
        acc[2][0] = fmaf(wa.z, xv.x, acc[2][0]); acc[2][1] = fmaf(wa.z, xv.y, acc[2][1]);
        acc[3][0] = fmaf(wa.w, xv.x, acc[3][0]); acc[3][1] = fmaf(wa.w, xv.y, acc[3][1]);
        acc[4][0] = fmaf(wb.x, xv.x, acc[4][0]); acc[4][1] = fmaf(wb.x, xv.y, acc[4][1]);
        acc[5][0] = fmaf(wb.y, xv.x, acc[5][0]); acc[5][1] = fmaf(wb.y, xv.y, acc[5][1]);
        acc[6][0] = fmaf(wb.z, xv.x, acc[6][0]); acc[6][1] = fmaf(wb.z, xv.y, acc[6][1]);
        acc[7][0] = fmaf(wb.w, xv.x, acc[7][0]); acc[7][1] = fmaf(wb.w, xv.y, acc[7][1]);
    }
#pragma unroll
    for (int h = 0; h < 8; h++) {
        float d = __shfl_sync(0xffffffffu, denom, h);
        float inv = 1.f / (d + 1e-16f);
        ((float2*)(g_H + w * 512 + h * 64))[lane] =
            make_float2(acc[h][0] * inv, acc[h][1] * inv);
    }
}

// ---------------- fused GEMM via tf32x3 tensor cores ----------------
#define SM_A  0
#define SM_W1 (128 * 68)
#define SM_W2 (SM_W1 + 64 * 68)
#define SM_P  (SM_W2 + 64 * 68)
#define GSMF  (SM_P + 8 * 16 * 68)
__global__ __launch_bounds__(256) void k_gemmF(const float* __restrict__ Wh,
                                               const float* __restrict__ Wo,
                                               const float* __restrict__ a_out) {
    extern __shared__ float sm[];
    float* sA  = sm + SM_A;
    float* sW1 = sm + SM_W1;
    float* sW2 = sm + SM_W2;
    int t = threadIdx.x;
    int r0 = blockIdx.x * 128;
    int warp = t >> 5, lane = t & 31;
    int g = lane >> 2, q = lane & 3;
    int wm = warp * 16;
    float* sPw = sm + SM_P + warp * (16 * 68);

    float C2[8][4] = {};

    for (int h = 0; h < 8; h++) {
        __syncthreads();
#pragma unroll
        for (int i = 0; i < 8; i++) {
            int idx = i * 256 + t;
            int m = idx >> 4, kq = idx & 15;
            float4 v = make_float4(0, 0, 0, 0);
            if (r0 + m < NN) v = *(const float4*)(g_H + (r0 + m) * 512 + h * 64 + kq * 4);
            *(float4*)(sA + m * 68 + kq * 4) = v;
        }
#pragma unroll
        for (int i = 0; i < 4; i++) {
            int idx = i * 256 + t;
            int k = idx >> 4, jq = idx & 15;
            *(float4*)(sW1 + k * 68 + jq * 4) = *(const float4*)(Wh + h * 4096 + k * 64 + jq * 4);
            *(float4*)(sW2 + k * 68 + jq * 4) = *(const float4*)(Wo + (h * 64 + k) * 64 + jq * 4);
        }
        __syncthreads();

        float C1[8][4] = {};
        for (int ks = 0; ks < 8; ks++) {
            int k0 = ks * 8;
            uint32_t ah[4], al[4];
            {
                const float* Ar = sA + (wm + g) * 68 + k0 + q;
                float a0 = Ar[0], a1 = Ar[8 * 68], a2 = Ar[4], a3 = Ar[8 * 68 + 4];
                tf32_split(a0, ah[0], al[0]);
                tf32_split(a1, ah[1], al[1]);
                tf32_split(a2, ah[2], al[2]);
                tf32_split(a3, ah[3], al[3]);
            }
#pragma unroll
            for (int nt = 0; nt < 8; nt++) {
                float b0f = sW1[(k0 + q) * 68 + nt * 8 + g];
                float b1f = sW1[(k0 + q + 4) * 68 + nt * 8 + g];
                uint32_t bh0, bl0, bh1, bl1;
                tf32_split(b0f, bh0, bl0);
                tf32_split(b1f, bh1, bl1);
                mma_tf32(C1[nt], ah, bh0, bh1);
                mma_tf32(C1[nt], ah, bl0, bl1);
                mma_tf32(C1[nt], al, bh0, bh1);
            }
        }
#pragma unroll
        for (int nt = 0; nt < 8; nt++) {
            *(float2*)(sPw + g * 68 + nt * 8 + 2 * q) =
                make_float2(elu1(elu1(C1[nt][0])), elu1(elu1(C1[nt][1])));
            *(float2*)(sPw + (g + 8) * 68 + nt * 8 + 2 * q) =
                make_float2(elu1(elu1(C1[nt][2])), elu1(elu1(C1[nt][3])));
        }
        __syncwarp();

        for (int ks = 0; ks < 8; ks++) {
            int k0 = ks * 8;
            uint32_t ah[4], al[4];
            {
                const float* Pr = sPw + g * 68 + k0 + q;
                float a0 = Pr[0], a1 = Pr[8 * 68], a2 = Pr[4], a3 = Pr[8 * 68 + 4];
                tf32_split(a0, ah[0], al[0]);
                tf32_split(a1, ah[1], al[1]);
                tf32_split(a2, ah[2], al[2]);
                tf32_split(a3, ah[3], al[3]);
            }
#pragma unroll
            for (int nt = 0; nt < 8; nt++) {
                float b0f = sW2[(k0 + q) * 68 + nt * 8 + g];
                float b1f = sW2[(k0 + q + 4) * 68 + nt * 8 + g];
                uint32_t bh0, bl0, bh1, bl1;
                tf32_split(b0f, bh0, bl0);
                tf32_split(b1f, bh1, bl1);
                mma_tf32(C2[nt], ah, bh0, bh1);
                mma_tf32(C2[nt], ah, bl0, bl1);
                mma_tf32(C2[nt], al, bh0, bh1);
            }
        }
        __syncwarp();
    }

    int rowA = r0 + wm + g;
    int rowB = rowA + 8;
    float p1a = 0.f, p2a = 0.f, p1b = 0.f, p2b = 0.f;
#pragma unroll
    for (int nt = 0; nt < 8; nt++) {
        int c = nt * 8 + 2 * q;
        float w0 = __ldg(a_out + c), w1 = __ldg(a_out + c + 1);
        float v0 = __ldg(a_out + 64 + c), v1 = __ldg(a_out + 64 + c + 1);
        p1a += C2[nt][0] * w0 + C2[nt][1] * w1;
        p2a += C2[nt][0] * v0 + C2[nt][1] * v1;
        p1b += C2[nt][2] * w0 + C2[nt][3] * w1;
        p2b += C2[nt][2] * v0 + C2[nt][3] * v1;
        if (rowA < NN)
            *(float2*)(g_h2 + rowA * 64 + c) = make_float2(C2[nt][0], C2[nt][1]);
        if (rowB < NN)
            *(float2*)(g_h2 + rowB * 64 + c) = make_float2(C2[nt][2], C2[nt][3]);
    }
#pragma unroll
    for (int off = 2; off > 0; off >>= 1) {
        p1a += __shfl_down_sync(0xffffffffu, p1a, off, 4);
        p2a += __shfl_down_sync(0xffffffffu, p2a, off, 4);
        p1b += __shfl_down_sync(0xffffffffu, p1b, off, 4);
        p2b += __shfl_down_sync(0xffffffffu, p2b, off, 4);
    }
    if (q == 0) {
        if (rowA < NN) { g_t1[rowA] = p1a; g_t2[rowA] = p2a; }
        if (rowB < NN) { g_t1[rowB] = p1b; g_t2[rowB] = p2b; }
    }
}

// ---------------- layer-2 edge weights: node-parallel (warp per node) ----------------
__global__ __launch_bounds__(256) void k_wgt2() {
    int n = (blockIdx.x * blockDim.x + threadIdx.x) >> 5;
    if (n >= NN) return;
    int lane = threadIdx.x & 31;
    int beg = g_offsets[n], end = g_offsets[n + 1];
    float t1v = g_t1[n];
    for (int i = beg + lane; i < end; i += 32) {
        int tg = g_tgt_sorted[i];
        float sc = leaky(t1v + g_t2[tg] + g_ea2_sorted[i]);
        g_ea2_sorted[i] = __expf(sc);
    }
}

// ---------------- layer-2 aggregation + log_softmax ----------------
__global__ __launch_bounds__(256) void k_agg2(float* __restrict__ out) {
    int n = (blockIdx.x * blockDim.x + threadIdx.x) >> 5;
    if (n >= NN) return;
    int lane = threadIdx.x & 31;
    int beg = g_offsets[n], end = g_offsets[n + 1];
    float acc0 = 0.f, acc1 = 0.f, denom = 0.f;
#pragma unroll 4
    for (int i = beg; i < end; i++) {
        int tg = g_tgt_sorted[i];
        float wgt = g_ea2_sorted[i];
        denom += wgt;
        float2 hv = ((const float2*)(g_h2 + tg * 64))[lane];
        acc0 = fmaf(wgt, hv.x, acc0);
        acc1 = fmaf(wgt, hv.y, acc1);
    }
    float inv = 1.f / (denom + 1e-16f);
    float y0 = elu1(acc0 * inv);
    float y1 = elu1(acc1 * inv);
    float m = fmaxf(y0, y1);
#pragma unroll
    for (int o = 16; o > 0; o >>= 1) m = fmaxf(m, __shfl_xor_sync(0xffffffffu, m, o));
    float se = __expf(y0 - m) + __expf(y1 - m);
#pragma unroll
    for (int o = 16; o > 0; o >>= 1) se += __shfl_xor_sync(0xffffffffu, se, o);
    float ls = m + logf(se);
    ((float2*)(out + n * 64))[lane] = make_float2(y0 - ls, y1 - ls);
}

// ---------------- launcher ----------------
extern "C" void kernel_launch(void* const* d_in, const int* in_sizes, int n_in,
                              void* d_out, int out_size) {
    const float* X        = (const float*)d_in[0];
    const float* ea       = (const float*)d_in[1];
    const float* W_heads  = (const float*)d_in[2];
    const float* a_heads  = (const float*)d_in[3];
    const float* W_out    = (const float*)d_in[4];
    const float* a_out    = (const float*)d_in[5];
    const int*   eidx     = (const int*)d_in[6];
    const int* src = eidx;
    const int* tgt = eidx + NE;
    float* out = (float*)d_out;

    size_t gsm = GSMF * sizeof(float);
    cudaFuncSetAttribute(k_gemmF, cudaFuncAttributeMaxDynamicSharedMemorySize, gsm);

    k_pre<<<49, 1024>>>(W_heads, a_heads);          // 0
    k_s12<<<(NN + 63) / 64, 256>>>(X);              // 1
    k_hist<<<(NE / 2 + 255) / 256, 256>>>(src);     // 2
    k_scan1<<<49, 1024>>>();                        // 3
    k_scan2<<<1, 32>>>();                           // 4
    k_scan3<<<49, 1024>>>();                        // 5
    k_scatter<<<(NE + 255) / 256, 256>>>(src, tgt, ea, a_heads, a_out);  // 6
    k_agg1<<<(NN * 32 + 255) / 256, 256>>>(X);      // 7
    k_gemmF<<<(NN + 127) / 128, 256, gsm>>>(W_heads, W_out, a_out);      // 8
    k_wgt2<<<(NN * 32 + 255) / 256, 256>>>();       // 9
    k_agg2<<<(NN * 32 + 255) / 256, 256>>>(out);    // 10
}